// round 3
// baseline (speedup 1.0000x reference)
#include <cuda_runtime.h>

// Conv2d: x[16][32][256][256] (NCHW) * w[32][32][3][3] (OIHW) + bias[32]
// stride 1, pad 1, dilation 1, groups 1. Output fp32 [16][32][256][256].
//
// Strategy: direct conv, one CTA = 16(h) x 32(w) output tile, ALL 32 C_out.
// Packed dual-FMA (fma.rn.f32x2) for 2x fp32 throughput on sm_103a.

#define TH 16
#define TW 32
#define IN_ROWS 18            // TH + 2 halo
#define IN_COLS 34            // TW + 2 halo
#define IN_STRIDE 35          // bank-conflict-free padding (3*hh + 8*wg mod 32 distinct)
#define C_IN 32
#define C_OUT 32
#define SMEM_IN_FLOATS (C_IN * IN_ROWS * IN_STRIDE)   // 32*18*35 = 20160
#define SMEM_W_FLOATS  (C_IN * 9 * 2 * C_OUT)         // duplicated weights: 18432
#define SMEM_BYTES ((SMEM_IN_FLOATS + SMEM_W_FLOATS) * 4)  // 154368 B

__device__ __forceinline__ unsigned long long pk2(float a, float b) {
    unsigned long long r;
    asm("mov.b64 %0, {%1, %2};" : "=l"(r) : "f"(a), "f"(b));
    return r;
}
__device__ __forceinline__ void upk2(unsigned long long v, float &a, float &b) {
    asm("mov.b64 {%0, %1}, %2;" : "=f"(a), "=f"(b) : "l"(v));
}
// packed dual fp32 FMA: d.lo = a.lo*b.lo + d.lo ; d.hi = a.hi*b.hi + d.hi
__device__ __forceinline__ void fma2(unsigned long long &d, unsigned long long a,
                                     unsigned long long b) {
    asm("fma.rn.f32x2 %0, %1, %2, %0;" : "+l"(d) : "l"(a), "l"(b));
}

__global__ __launch_bounds__(256, 1)
void conv3x3_f32x2_kernel(const float* __restrict__ x,
                          const float* __restrict__ wt,
                          const float* __restrict__ bias,
                          float* __restrict__ out)
{
    extern __shared__ float smem[];
    float* s_in = smem;                      // [ci][18][35]
    float* s_w  = smem + SMEM_IN_FLOATS;     // [ci][kh][kw][2*co] (each weight duplicated)

    const int tid = threadIdx.x;
    const int n   = blockIdx.z;
    const int H0  = blockIdx.y * TH;
    const int W0  = blockIdx.x * TW;

    // ---- cooperative load: weights, each duplicated {w,w} for packed FMA ----
    // global: wt[co][ci][kh][kw]; smem: s_w[((ci*3+kh)*3+kw)*64 + 2*co + {0,1}]
    for (int i = tid; i < C_OUT * C_IN * 9; i += 256) {
        int co  = i / (C_IN * 9);
        int rem = i - co * (C_IN * 9);       // rem = ci*9 + k
        float v = __ldg(wt + i);
        int o = rem * 64 + 2 * co;
        s_w[o]     = v;
        s_w[o + 1] = v;
    }

    // ---- cooperative load: input tile + halo (zero-padded) ----
    const float* xin = x + (size_t)n * C_IN * 256 * 256;
    for (int idx = tid; idx < C_IN * IN_ROWS * IN_COLS; idx += 256) {
        int ci  = idx / (IN_ROWS * IN_COLS);
        int rem = idx - ci * (IN_ROWS * IN_COLS);
        int r   = rem / IN_COLS;
        int c   = rem - r * IN_COLS;
        int gh  = H0 - 1 + r;
        int gw  = W0 - 1 + c;
        float v = 0.0f;
        if ((unsigned)gh < 256u && (unsigned)gw < 256u)
            v = __ldg(xin + ci * 65536 + gh * 256 + gw);
        s_in[ci * (IN_ROWS * IN_STRIDE) + r * IN_STRIDE + c] = v;
    }
    __syncthreads();

    // ---- thread mapping: 4 cout-groups x 16 rows x 4 w-groups ----
    const int cg      = tid >> 6;            // 0..3
    const int co_base = cg * 8;
    const int rem     = tid & 63;
    const int hh      = rem >> 2;            // 0..15
    const int wbase   = (rem & 3) * 8;       // 0,8,16,24

    // 8 couts x 4 pixel-pairs (8 consecutive w) per thread, bias pre-loaded
    unsigned long long acc[8][4];
    #pragma unroll
    for (int i = 0; i < 8; i++) {
        float bv = __ldg(bias + co_base + i);
        unsigned long long bp = pk2(bv, bv);
        #pragma unroll
        for (int p = 0; p < 4; p++) acc[i][p] = bp;
    }

    const float* s_in_base = s_in + hh * IN_STRIDE + wbase;

    #pragma unroll 1
    for (int ci = 0; ci < C_IN; ci++) {
        #pragma unroll
        for (int kh = 0; kh < 3; kh++) {
            const float* row = s_in_base + ci * (IN_ROWS * IN_STRIDE) + kh * IN_STRIDE;
            float in_r[10];
            #pragma unroll
            for (int j = 0; j < 10; j++) in_r[j] = row[j];

            #pragma unroll
            for (int kw = 0; kw < 3; kw++) {
                // 8 duplicated weights = 4 x 16B loads (warp-uniform -> smem broadcast)
                unsigned long long wv[8];
                const ulonglong2* wp =
                    (const ulonglong2*)s_w + ((ci * 3 + kh) * 3 + kw) * 16 + cg * 4;
                #pragma unroll
                for (int q = 0; q < 4; q++) {
                    ulonglong2 t = wp[q];
                    wv[2 * q]     = t.x;
                    wv[2 * q + 1] = t.y;
                }
                // pack input pairs for this kw shift
                unsigned long long ip[4];
                #pragma unroll
                for (int p = 0; p < 4; p++)
                    ip[p] = pk2(in_r[kw + 2 * p], in_r[kw + 2 * p + 1]);
                // 32 packed FMAs = 64 fp32 FMAs
                #pragma unroll
                for (int co = 0; co < 8; co++) {
                    #pragma unroll
                    for (int p = 0; p < 4; p++)
                        fma2(acc[co][p], wv[co], ip[p]);
                }
            }
        }
    }

    // ---- store: 2x float4 per cout, fully coalesced across the warp ----
    float* obase = out + (((size_t)n * C_OUT + co_base) * 256 + (H0 + hh)) * 256
                       + W0 + wbase;
    #pragma unroll
    for (int co = 0; co < 8; co++) {
        float4 v0, v1;
        upk2(acc[co][0], v0.x, v0.y);
        upk2(acc[co][1], v0.z, v0.w);
        upk2(acc[co][2], v1.x, v1.y);
        upk2(acc[co][3], v1.z, v1.w);
        float* op = obase + (size_t)co * 65536;
        *(float4*)(op)     = v0;
        *(float4*)(op + 4) = v1;
    }
}

extern "C" void kernel_launch(void* const* d_in, const int* in_sizes, int n_in,
                              void* d_out, int out_size)
{
    const float* x    = (const float*)d_in[0];
    const float* wt   = (const float*)d_in[1];
    const float* bias = (const float*)d_in[2];
    float* out        = (float*)d_out;

    // >48KB dynamic smem needs opt-in; non-stream API, idempotent, capture-safe.
    cudaFuncSetAttribute(conv3x3_f32x2_kernel,
                         cudaFuncAttributeMaxDynamicSharedMemorySize, SMEM_BYTES);

    dim3 grid(256 / TW, 256 / TH, 16);   // (8, 16, 16) = 2048 CTAs
    conv3x3_f32x2_kernel<<<grid, 256, SMEM_BYTES>>>(x, wt, bias, out);
}

// round 7
// speedup vs baseline: 1.2576x; 1.2576x over previous
#include <cuda_runtime.h>

// Conv2d: x[16][32][256][256] (NCHW) * w[32][32][3][3] (OIHW) + bias[32]
// fp32, stride 1, pad 1. Direct conv, packed dual-FMA (fma.rn.f32x2).
//
// 2 CTAs/SM (ci split into 2 halves -> 85KB smem/CTA), LDS.64 pre-packed
// input pairs (IN_STRIDE=42, 8B-aligned, bank-conflict-free).

#define TH 16
#define TW 32
#define IN_ROWS 18            // TH + 2 halo
#define IN_COLS 34            // TW + 2 halo
#define IN_STRIDE 42          // even (LDS.64-aligned) + conflict-free: (5hh+4wg+j) mod 16 injective
#define C_IN 32
#define C_OUT 32
#define HALF_C 16             // channels staged per pass
#define SMEM_IN_FLOATS (HALF_C * IN_ROWS * IN_STRIDE)   // 16*18*42 = 12096
#define SMEM_W_FLOATS  (HALF_C * 9 * 2 * C_OUT)         // 16*9*64  = 9216
#define SMEM_BYTES ((SMEM_IN_FLOATS + SMEM_W_FLOATS) * 4)  // 85248 B

__device__ __forceinline__ unsigned long long pk2(float a, float b) {
    unsigned long long r;
    asm("mov.b64 %0, {%1, %2};" : "=l"(r) : "f"(a), "f"(b));
    return r;
}
__device__ __forceinline__ void upk2(unsigned long long v, float &a, float &b) {
    asm("mov.b64 {%0, %1}, %2;" : "=f"(a), "=f"(b) : "l"(v));
}
// packed dual fp32 FMA: d.lo += a.lo*b.lo ; d.hi += a.hi*b.hi
__device__ __forceinline__ void fma2(unsigned long long &d, unsigned long long a,
                                     unsigned long long b) {
    asm("fma.rn.f32x2 %0, %1, %2, %0;" : "+l"(d) : "l"(a), "l"(b));
}

__global__ __launch_bounds__(256, 2)
void conv3x3_f32x2_kernel(const float* __restrict__ x,
                          const float* __restrict__ wt,
                          const float* __restrict__ bias,
                          float* __restrict__ out)
{
    extern __shared__ float smem[];
    float* s_in = smem;                      // [ci'][18][42]
    float* s_w  = smem + SMEM_IN_FLOATS;     // [ci'][kh][kw][2*co] (weights duplicated)

    const int tid = threadIdx.x;
    const int n   = blockIdx.z;
    const int H0  = blockIdx.y * TH;
    const int W0  = blockIdx.x * TW;

    // ---- thread mapping: 4 cout-groups x 16 rows x 4 w-groups ----
    const int cg      = tid >> 6;            // 0..3
    const int co_base = cg * 8;
    const int rem     = tid & 63;
    const int hh      = rem >> 2;            // 0..15
    const int wbase   = (rem & 3) * 8;       // 0,8,16,24

    // 8 couts x 4 pixel-pairs per thread, bias pre-loaded
    unsigned long long acc[8][4];
    #pragma unroll
    for (int i = 0; i < 8; i++) {
        float bv = __ldg(bias + co_base + i);
        unsigned long long bp = pk2(bv, bv);
        #pragma unroll
        for (int p = 0; p < 4; p++) acc[i][p] = bp;
    }

    const float* xin = x + (size_t)n * C_IN * 65536;
    const float* s_in_base = s_in + hh * IN_STRIDE + wbase;

    #pragma unroll 1
    for (int half = 0; half < 2; half++) {
        // ---- stage weights for this ci-half, duplicated {w,w} ----
        // gmem: wt[co][ci][kh][kw]; smem: s_w[(ci'*9+k)*64 + 2*co + {0,1}]
        for (int i = tid; i < C_OUT * HALF_C * 9; i += 256) {
            int co   = i / (HALF_C * 9);
            int rem2 = i - co * (HALF_C * 9);          // ci'*9 + k
            float v  = __ldg(wt + co * (C_IN * 9) + half * (HALF_C * 9) + rem2);
            int o = rem2 * 64 + 2 * co;
            s_w[o]     = v;
            s_w[o + 1] = v;
        }
        // ---- stage input half-tile + halo (zero-padded) ----
        for (int idx = tid; idx < HALF_C * IN_ROWS * IN_COLS; idx += 256) {
            int ci   = idx / (IN_ROWS * IN_COLS);
            int rem2 = idx - ci * (IN_ROWS * IN_COLS);
            int r    = rem2 / IN_COLS;
            int c    = rem2 - r * IN_COLS;
            int gh   = H0 - 1 + r;
            int gw   = W0 - 1 + c;
            float v = 0.0f;
            if ((unsigned)gh < 256u && (unsigned)gw < 256u)
                v = __ldg(xin + (half * HALF_C + ci) * 65536 + gh * 256 + gw);
            s_in[ci * (IN_ROWS * IN_STRIDE) + r * IN_STRIDE + c] = v;
        }
        __syncthreads();

        #pragma unroll 1
        for (int ci = 0; ci < HALF_C; ci++) {
            #pragma unroll
            for (int kh = 0; kh < 3; kh++) {
                const float* rowp = s_in_base + ci * (IN_ROWS * IN_STRIDE)
                                             + kh * IN_STRIDE;
                // 5 x LDS.64: pre-packed pairs (0,1)(2,3)(4,5)(6,7)(8,9)
                unsigned long long pr[5];
                #pragma unroll
                for (int j = 0; j < 5; j++)
                    pr[j] = *(const unsigned long long*)(rowp + 2 * j);
                // kw=1 needs shifted pairs (1,2)(3,4)(5,6)(7,8)
                float sc[10];
                #pragma unroll
                for (int j = 0; j < 5; j++) upk2(pr[j], sc[2 * j], sc[2 * j + 1]);
                unsigned long long ip1[4];
                #pragma unroll
                for (int p = 0; p < 4; p++)
                    ip1[p] = pk2(sc[2 * p + 1], sc[2 * p + 2]);

                #pragma unroll
                for (int kw = 0; kw < 3; kw++) {
                    // 8 duplicated weights = 4x LDS.128 (warp-uniform broadcast)
                    unsigned long long wv[8];
                    const ulonglong2* wp =
                        (const ulonglong2*)s_w + ((ci * 3 + kh) * 3 + kw) * 16 + cg * 4;
                    #pragma unroll
                    for (int q = 0; q < 4; q++) {
                        ulonglong2 t = wp[q];
                        wv[2 * q]     = t.x;
                        wv[2 * q + 1] = t.y;
                    }
                    #pragma unroll
                    for (int co = 0; co < 8; co++) {
                        #pragma unroll
                        for (int p = 0; p < 4; p++)
                            fma2(acc[co][p],
                                 wv[co],
                                 (kw == 0) ? pr[p] : (kw == 1) ? ip1[p] : pr[p + 1]);
                    }
                }
            }
        }
        __syncthreads();   // buffers reused by next half
    }

    // ---- store: 2x float4 per cout, fully coalesced ----
    float* obase = out + (((size_t)n * C_OUT + co_base) * 256 + (H0 + hh)) * 256
                       + W0 + wbase;
    #pragma unroll
    for (int co = 0; co < 8; co++) {
        float4 v0, v1;
        upk2(acc[co][0], v0.x, v0.y);
        upk2(acc[co][1], v0.z, v0.w);
        upk2(acc[co][2], v1.x, v1.y);
        upk2(acc[co][3], v1.z, v1.w);
        float* op = obase + (size_t)co * 65536;
        *(float4*)(op)     = v0;
        *(float4*)(op + 4) = v1;
    }
}

extern "C" void kernel_launch(void* const* d_in, const int* in_sizes, int n_in,
                              void* d_out, int out_size)
{
    const float* x    = (const float*)d_in[0];
    const float* wt   = (const float*)d_in[1];
    const float* bias = (const float*)d_in[2];
    float* out        = (float*)d_out;

    cudaFuncSetAttribute(conv3x3_f32x2_kernel,
                         cudaFuncAttributeMaxDynamicSharedMemorySize, SMEM_BYTES);

    dim3 grid(256 / TW, 256 / TH, 16);   // (8, 16, 16) = 2048 CTAs
    conv3x3_f32x2_kernel<<<grid, 256, SMEM_BYTES>>>(x, wt, bias, out);
}